// round 1
// baseline (speedup 1.0000x reference)
#include <cuda_runtime.h>

#define D     1024
#define HD    4096
#define LNUM  12
#define VOCAB 50257
#define NT    256
#define NW    8

// ---------------- global scratch (no allocations allowed) ----------------
__device__ float g_x[D];
__device__ float g_k[D];
__device__ float g_v[D];
__device__ float g_r[D];
__device__ float g_k2[HD];
__device__ float g_r2[D];

// ---------------- 2-level software grid barrier ----------------
__device__ unsigned g_bar_gen = 0;
__device__ unsigned g_leaf[8 * 128];   // 512B stride between leaf counters
__device__ unsigned g_root = 0;

__device__ __forceinline__ void grid_barrier(int nb) {
    __syncthreads();
    if (threadIdx.x == 0) {
        __threadfence();
        unsigned gen = *((volatile unsigned*)&g_bar_gen);
        int leaf = blockIdx.x & 7;
        unsigned target = (unsigned)((nb >> 3) + ((blockIdx.x & 7) < (nb & 7) ? 1 : 0));
        if (atomicAdd(&g_leaf[leaf * 128], 1u) == target - 1u) {
            g_leaf[leaf * 128] = 0;
            __threadfence();
            if (atomicAdd(&g_root, 1u) == 7u) {
                g_root = 0;
                __threadfence();
                atomicAdd(&g_bar_gen, 1u);
            }
        }
        while (*((volatile unsigned*)&g_bar_gen) == gen) { }
        __threadfence();
    }
    __syncthreads();
}

// ---------------- block-wide sum ----------------
__device__ __forceinline__ float block_sum(float v, float* sred) {
    int lane = threadIdx.x & 31, wid = threadIdx.x >> 5;
    #pragma unroll
    for (int o = 16; o; o >>= 1) v += __shfl_xor_sync(0xffffffffu, v, o);
    if (lane == 0) sred[wid] = v;
    __syncthreads();
    float t = 0.f;
    if (wid == 0) {
        t = (lane < NW) ? sred[lane] : 0.f;
        #pragma unroll
        for (int o = 4; o; o >>= 1) t += __shfl_xor_sync(0xffffffffu, t, o);
        if (lane == 0) sred[0] = t;
    }
    __syncthreads();
    float r = sred[0];
    __syncthreads();
    return r;
}

// ---------------- warp-level dot: row (global) . vec (shared) ----------------
// c128 = row_len / 128 (8 for 1024, 32 for 4096)
__device__ __forceinline__ float warp_dot(const float* __restrict__ w,
                                          const float* __restrict__ vec, int c128) {
    const int lane = threadIdx.x & 31;
    const float4* w4 = reinterpret_cast<const float4*>(w);
    const float4* v4 = reinterpret_cast<const float4*>(vec);
    float ax = 0.f, ay = 0.f, az = 0.f, aw = 0.f;
    #pragma unroll 8
    for (int c = 0; c < c128; c++) {
        float4 a = __ldg(w4 + c * 32 + lane);
        float4 b = v4[c * 32 + lane];
        ax = fmaf(a.x, b.x, ax);
        ay = fmaf(a.y, b.y, ay);
        az = fmaf(a.z, b.z, az);
        aw = fmaf(a.w, b.w, aw);
    }
    float acc = (ax + ay) + (az + aw);
    #pragma unroll
    for (int o = 16; o; o >>= 1) acc += __shfl_xor_sync(0xffffffffu, acc, o);
    return acc;
}

__global__ __launch_bounds__(NT, 1) void rwkv_persistent(
    const int*   __restrict__ ctx,
    const float* __restrict__ st_in,
    const float* __restrict__ emb,
    const float* __restrict__ ln0,
    const float* __restrict__ ln1,
    const float* __restrict__ ln2,
    const float* __restrict__ lnout,
    const float* __restrict__ tmk,
    const float* __restrict__ tmv,
    const float* __restrict__ tmr,
    const float* __restrict__ tfirst,
    const float* __restrict__ tdecay,
    const float* __restrict__ kw,
    const float* __restrict__ vw,
    const float* __restrict__ rw,
    const float* __restrict__ ow,
    const float* __restrict__ ftmk,
    const float* __restrict__ ftmr,
    const float* __restrict__ fkw,
    const float* __restrict__ fvw,
    const float* __restrict__ frw,
    const float* __restrict__ head,
    float* __restrict__ out,
    int nb)
{
    __shared__ float sbuf[4096];
    __shared__ float sred[NW];

    const int tid  = threadIdx.x;
    const int lane = tid & 31;
    const int gw   = blockIdx.x * NW + (tid >> 5);
    const int nwG  = nb * NW;

    float* out_logits = out;
    float* out_state  = out + VOCAB;

    // ---------- stage 0: x = rms(emb[ctx[0]], ln0) ----------
    if (blockIdx.x == 0) {
        const float* e = emb + (size_t)ctx[0] * D;
        float ss = 0.f;
        for (int j = tid; j < D; j += NT) { float t = e[j]; ss += t * t; }
        ss = block_sum(ss, sred);
        float inv = rsqrtf(ss * (1.f / D) + 1e-5f);
        for (int j = tid; j < D; j += NT) g_x[j] = e[j] * inv * ln0[j];
    }
    grid_barrier(nb);

    for (int l = 0; l < LNUM; l++) {
        const float* st_l  = st_in     + (size_t)l * 5 * D;
        float*       ost_l = out_state + (size_t)l * 5 * D;

        // ---------- stage A: xx = rms(x,l1); token-mix; k,v,r matvecs ----------
        {
            float ss = 0.f;
            for (int j = tid; j < D; j += NT) { float t = g_x[j]; ss += t * t; }
            ss = block_sum(ss, sred);
            float inv = rsqrtf(ss * (1.f / D) + 1e-5f);
            const float* l1 = ln1 + l * D;
            const float* mk = tmk + l * D;
            const float* mv = tmv + l * D;
            const float* mr = tmr + l * D;
            for (int j = tid; j < D; j += NT) {
                float xxj = g_x[j] * inv * l1[j];
                float sa  = st_l[D + j];
                float a_ = mk[j]; sbuf[j]         = xxj * a_ + sa * (1.f - a_);
                float b_ = mv[j]; sbuf[D + j]     = xxj * b_ + sa * (1.f - b_);
                float c_ = mr[j]; sbuf[2 * D + j] = xxj * c_ + sa * (1.f - c_);
                if (blockIdx.x == 0) ost_l[D + j] = xxj;   // new sa_x
            }
            __syncthreads();
            const float* kwl = kw + (size_t)l * D * D;
            const float* vwl = vw + (size_t)l * D * D;
            const float* rwl = rw + (size_t)l * D * D;
            for (int row = gw; row < 3 * D; row += nwG) {
                float r;
                if (row < D) {
                    r = warp_dot(kwl + (size_t)row * D, sbuf, 8);
                    if (lane == 0) g_k[row] = r;
                } else if (row < 2 * D) {
                    r = warp_dot(vwl + (size_t)(row - D) * D, sbuf + D, 8);
                    if (lane == 0) g_v[row - D] = r;
                } else {
                    r = warp_dot(rwl + (size_t)(row - 2 * D) * D, sbuf + 2 * D, 8);
                    if (lane == 0) g_r[row - 2 * D] = r;
                }
            }
        }
        grid_barrier(nb);

        // ---------- stage B: WKV elementwise (redundant) + ow matvec ----------
        {
            const float* tfl = tfirst + l * D;
            const float* tdl = tdecay + l * D;
            for (int j = tid; j < D; j += NT) {
                float k  = g_k[j], v = g_v[j], rr = g_r[j];
                float aa = st_l[2 * D + j], bb = st_l[3 * D + j], pp = st_l[4 * D + j];
                float ww = tfl[j] + k;
                float p  = fmaxf(pp, ww);
                float e1 = __expf(pp - p), e2 = __expf(ww - p);
                float a  = e1 * aa + e2 * v;
                float b  = e1 * bb + e2;
                float sr = 1.f / (1.f + __expf(-rr));
                sbuf[j] = sr * (a / b);
                if (blockIdx.x == 0) {
                    float ww2 = pp + tdl[j];
                    float p2  = fmaxf(ww2, k);
                    float e1b = __expf(ww2 - p2), e2b = __expf(k - p2);
                    ost_l[2 * D + j] = e1b * aa + e2b * v;  // naa
                    ost_l[3 * D + j] = e1b * bb + e2b;      // nbb
                    ost_l[4 * D + j] = p2;                  // pp
                }
            }
            __syncthreads();
            const float* owl = ow + (size_t)l * D * D;
            for (int row = gw; row < D; row += nwG) {
                float dv = warp_dot(owl + (size_t)row * D, sbuf, 8);
                if (lane == 0) g_x[row] += dv;
            }
        }
        grid_barrier(nb);

        // ---------- stage C: yy = rms(x,l2); channel-mix; fkw (H) + frw (D) ----------
        {
            float ss = 0.f;
            for (int j = tid; j < D; j += NT) { float t = g_x[j]; ss += t * t; }
            ss = block_sum(ss, sred);
            float inv = rsqrtf(ss * (1.f / D) + 1e-5f);
            const float* l2l = ln2  + l * D;
            const float* fmk = ftmk + l * D;
            const float* fmr = ftmr + l * D;
            for (int j = tid; j < D; j += NT) {
                float yyj = g_x[j] * inv * l2l[j];
                float ff  = st_l[j];
                float a_ = fmk[j]; sbuf[j]     = yyj * a_ + ff * (1.f - a_);
                float b_ = fmr[j]; sbuf[D + j] = yyj * b_ + ff * (1.f - b_);
                if (blockIdx.x == 0) ost_l[j] = yyj;   // new ff_x
            }
            __syncthreads();
            const float* fkwl = fkw + (size_t)l * HD * D;
            const float* frwl = frw + (size_t)l * D * D;
            for (int row = gw; row < HD + D; row += nwG) {
                if (row < HD) {
                    float t = warp_dot(fkwl + (size_t)row * D, sbuf, 8);
                    if (lane == 0) { t = fmaxf(t, 0.f); g_k2[row] = t * t; }
                } else {
                    float t = warp_dot(frwl + (size_t)(row - HD) * D, sbuf + D, 8);
                    if (lane == 0) g_r2[row - HD] = t;
                }
            }
        }
        grid_barrier(nb);

        // ---------- stage D: x = (x + sigmoid(r2) * (fvw @ k2)) * sc ----------
        {
            for (int j = tid; j < HD; j += NT) sbuf[j] = g_k2[j];
            __syncthreads();
            const float sc = ((l + 1) % 6 == 0) ? 0.5f : 1.0f;
            const float* fvwl = fvw + (size_t)l * D * HD;
            for (int row = gw; row < D; row += nwG) {
                float acc = warp_dot(fvwl + (size_t)row * HD, sbuf, 32);
                if (lane == 0) {
                    float sr = 1.f / (1.f + __expf(-g_r2[row]));
                    g_x[row] = (g_x[row] + sr * acc) * sc;
                }
            }
        }
        grid_barrier(nb);
    }

    // ---------- head: logits = head @ rms(x, lnout) ----------
    {
        float ss = 0.f;
        for (int j = tid; j < D; j += NT) { float t = g_x[j]; ss += t * t; }
        ss = block_sum(ss, sred);
        float inv = rsqrtf(ss * (1.f / D) + 1e-5f);
        for (int j = tid; j < D; j += NT) sbuf[j] = g_x[j] * inv * lnout[j];
        __syncthreads();
        for (int row = gw; row < VOCAB; row += nwG) {
            float t = warp_dot(head + (size_t)row * D, sbuf, 8);
            if (lane == 0) out_logits[row] = t;
        }
    }
}

extern "C" void kernel_launch(void* const* d_in, const int* in_sizes, int n_in,
                              void* d_out, int out_size) {
    (void)in_sizes; (void)n_in; (void)out_size;
    int nb = 0;
    cudaDeviceGetAttribute(&nb, cudaDevAttrMultiProcessorCount, 0);
    if (nb <= 0) nb = 148;
    if (nb > 1024) nb = 1024;

    rwkv_persistent<<<nb, NT>>>(
        (const int*)  d_in[0],   // ctx
        (const float*)d_in[1],   // state
        (const float*)d_in[2],   // emb
        (const float*)d_in[3],   // ln0_w
        (const float*)d_in[4],   // ln1_w
        (const float*)d_in[5],   // ln2_w
        (const float*)d_in[6],   // lnout_w
        (const float*)d_in[7],   // att_tmk
        (const float*)d_in[8],   // att_tmv
        (const float*)d_in[9],   // att_tmr
        (const float*)d_in[10],  // att_tfirst
        (const float*)d_in[11],  // att_tdecay
        (const float*)d_in[12],  // att_kw
        (const float*)d_in[13],  // att_vw
        (const float*)d_in[14],  // att_rw
        (const float*)d_in[15],  // att_ow
        (const float*)d_in[16],  // ffn_tmk
        (const float*)d_in[17],  // ffn_tmr
        (const float*)d_in[18],  // ffn_kw
        (const float*)d_in[19],  // ffn_vw
        (const float*)d_in[20],  // ffn_rw
        (const float*)d_in[21],  // head
        (float*)d_out, nb);
}

// round 2
// speedup vs baseline: 1.3017x; 1.3017x over previous
#include <cuda_runtime.h>

#define D     1024
#define HD    4096
#define LNUM  12
#define VOCAB 50257
#define NT    512
#define NW    16

// ---------------- global scratch (no allocations allowed) ----------------
__device__ float g_x[D];
__device__ float g_k[D];
__device__ float g_v[D];
__device__ float g_r[D];
__device__ float g_k2[HD];
__device__ float g_r2[D];

// ---------------- 2-level software grid barrier ----------------
__device__ unsigned g_bar_gen = 0;
__device__ unsigned g_leaf[8 * 128];   // 512B stride between leaf counters
__device__ unsigned g_root = 0;

__device__ __forceinline__ void grid_barrier(int nb) {
    __syncthreads();
    if (threadIdx.x == 0) {
        __threadfence();
        unsigned gen = *((volatile unsigned*)&g_bar_gen);
        int leaf = blockIdx.x & 7;
        unsigned target = (unsigned)((nb >> 3) + ((blockIdx.x & 7) < (nb & 7) ? 1 : 0));
        if (atomicAdd(&g_leaf[leaf * 128], 1u) == target - 1u) {
            g_leaf[leaf * 128] = 0;
            __threadfence();
            if (atomicAdd(&g_root, 1u) == 7u) {
                g_root = 0;
                __threadfence();
                atomicAdd(&g_bar_gen, 1u);
            }
        }
        while (*((volatile unsigned*)&g_bar_gen) == gen) { }
        __threadfence();
    }
    __syncthreads();
}

// ---------------- block-wide sum ----------------
__device__ __forceinline__ float block_sum(float v, float* sred) {
    int lane = threadIdx.x & 31, wid = threadIdx.x >> 5;
    #pragma unroll
    for (int o = 16; o; o >>= 1) v += __shfl_xor_sync(0xffffffffu, v, o);
    if (lane == 0) sred[wid] = v;
    __syncthreads();
    float t = 0.f;
    if (wid == 0) {
        t = (lane < NW) ? sred[lane] : 0.f;
        #pragma unroll
        for (int o = 8; o; o >>= 1) t += __shfl_xor_sync(0xffffffffu, t, o);
        if (lane == 0) sred[0] = t;
    }
    __syncthreads();
    float r = sred[0];
    __syncthreads();
    return r;
}

// ---------------- warp dot, row length = NB8*1024 floats ----------------
// Per 1024-float batch: 8 LDG.128 issued back-to-back (explicit batch so the
// FMAs cannot be interleaved before all loads are in flight), then consume.
template<int NB8>
__device__ __forceinline__ float warp_dotN(const float* __restrict__ w,
                                           const float* __restrict__ vec) {
    const int lane = threadIdx.x & 31;
    const float4* __restrict__ w4 = reinterpret_cast<const float4*>(w);
    const float4* __restrict__ v4 = reinterpret_cast<const float4*>(vec);
    float ax = 0.f, ay = 0.f, az = 0.f, aw = 0.f;
    #pragma unroll
    for (int b = 0; b < NB8; b++) {
        float4 a[8];
        #pragma unroll
        for (int i = 0; i < 8; i++)
            a[i] = __ldg(w4 + b * 256 + i * 32 + lane);
        #pragma unroll
        for (int i = 0; i < 8; i++) {
            float4 bv = v4[b * 256 + i * 32 + lane];
            ax = fmaf(a[i].x, bv.x, ax);
            ay = fmaf(a[i].y, bv.y, ay);
            az = fmaf(a[i].z, bv.z, az);
            aw = fmaf(a[i].w, bv.w, aw);
        }
    }
    float acc = (ax + ay) + (az + aw);
    #pragma unroll
    for (int o = 16; o; o >>= 1) acc += __shfl_xor_sync(0xffffffffu, acc, o);
    return acc;
}

__global__ __launch_bounds__(NT, 1) void rwkv_persistent(
    const int*   __restrict__ ctx,
    const float* __restrict__ st_in,
    const float* __restrict__ emb,
    const float* __restrict__ ln0,
    const float* __restrict__ ln1,
    const float* __restrict__ ln2,
    const float* __restrict__ lnout,
    const float* __restrict__ tmk,
    const float* __restrict__ tmv,
    const float* __restrict__ tmr,
    const float* __restrict__ tfirst,
    const float* __restrict__ tdecay,
    const float* __restrict__ kw,
    const float* __restrict__ vw,
    const float* __restrict__ rw,
    const float* __restrict__ ow,
    const float* __restrict__ ftmk,
    const float* __restrict__ ftmr,
    const float* __restrict__ fkw,
    const float* __restrict__ fvw,
    const float* __restrict__ frw,
    const float* __restrict__ head,
    float* __restrict__ out,
    int nb)
{
    __shared__ float sbuf[4096];
    __shared__ float sred[NW];

    const int tid  = threadIdx.x;
    const int lane = tid & 31;
    const int gw   = blockIdx.x * NW + (tid >> 5);
    const int nwG  = nb * NW;

    float* out_logits = out;
    float* out_state  = out + VOCAB;

    // ---------- stage 0: x = rms(emb[ctx[0]], ln0) ----------
    if (blockIdx.x == 0) {
        const float* e = emb + (size_t)ctx[0] * D;
        float ss = 0.f;
        for (int j = tid; j < D; j += NT) { float t = e[j]; ss += t * t; }
        ss = block_sum(ss, sred);
        float inv = rsqrtf(ss * (1.f / D) + 1e-5f);
        for (int j = tid; j < D; j += NT) g_x[j] = e[j] * inv * ln0[j];
    }
    grid_barrier(nb);

    for (int l = 0; l < LNUM; l++) {
        const float* st_l  = st_in     + (size_t)l * 5 * D;
        float*       ost_l = out_state + (size_t)l * 5 * D;

        // ---------- stage A: xx = rms(x,l1); token-mix; k,v,r matvecs ----------
        {
            float ss = 0.f;
            for (int j = tid; j < D; j += NT) { float t = g_x[j]; ss += t * t; }
            ss = block_sum(ss, sred);
            float inv = rsqrtf(ss * (1.f / D) + 1e-5f);
            const float* l1 = ln1 + l * D;
            const float* mk = tmk + l * D;
            const float* mv = tmv + l * D;
            const float* mr = tmr + l * D;
            for (int j = tid; j < D; j += NT) {
                float xxj = g_x[j] * inv * l1[j];
                float sa  = st_l[D + j];
                float a_ = mk[j]; sbuf[j]         = xxj * a_ + sa * (1.f - a_);
                float b_ = mv[j]; sbuf[D + j]     = xxj * b_ + sa * (1.f - b_);
                float c_ = mr[j]; sbuf[2 * D + j] = xxj * c_ + sa * (1.f - c_);
                if (blockIdx.x == 0) ost_l[D + j] = xxj;   // new sa_x
            }
            __syncthreads();
            const float* kwl = kw + (size_t)l * D * D;
            const float* vwl = vw + (size_t)l * D * D;
            const float* rwl = rw + (size_t)l * D * D;
            for (int row = gw; row < 3 * D; row += nwG) {
                float r;
                if (row < D) {
                    r = warp_dotN<1>(kwl + (size_t)row * D, sbuf);
                    if (lane == 0) g_k[row] = r;
                } else if (row < 2 * D) {
                    r = warp_dotN<1>(vwl + (size_t)(row - D) * D, sbuf + D);
                    if (lane == 0) g_v[row - D] = r;
                } else {
                    r = warp_dotN<1>(rwl + (size_t)(row - 2 * D) * D, sbuf + 2 * D);
                    if (lane == 0) g_r[row - 2 * D] = r;
                }
            }
        }
        grid_barrier(nb);

        // ---------- stage B: WKV elementwise (redundant) + ow matvec ----------
        {
            const float* tfl = tfirst + l * D;
            const float* tdl = tdecay + l * D;
            for (int j = tid; j < D; j += NT) {
                float k  = g_k[j], v = g_v[j], rr = g_r[j];
                float aa = st_l[2 * D + j], bb = st_l[3 * D + j], pp = st_l[4 * D + j];
                float ww = tfl[j] + k;
                float p  = fmaxf(pp, ww);
                float e1 = __expf(pp - p), e2 = __expf(ww - p);
                float a  = e1 * aa + e2 * v;
                float b  = e1 * bb + e2;
                float sr = 1.f / (1.f + __expf(-rr));
                sbuf[j] = sr * (a / b);
                if (blockIdx.x == 0) {
                    float ww2 = pp + tdl[j];
                    float p2  = fmaxf(ww2, k);
                    float e1b = __expf(ww2 - p2), e2b = __expf(k - p2);
                    ost_l[2 * D + j] = e1b * aa + e2b * v;  // naa
                    ost_l[3 * D + j] = e1b * bb + e2b;      // nbb
                    ost_l[4 * D + j] = p2;                  // pp
                }
            }
            __syncthreads();
            const float* owl = ow + (size_t)l * D * D;
            for (int row = gw; row < D; row += nwG) {
                float dv = warp_dotN<1>(owl + (size_t)row * D, sbuf);
                if (lane == 0) g_x[row] += dv;
            }
        }
        grid_barrier(nb);

        // ---------- stage C: yy = rms(x,l2); channel-mix; fkw (H) + frw (D) ----------
        {
            float ss = 0.f;
            for (int j = tid; j < D; j += NT) { float t = g_x[j]; ss += t * t; }
            ss = block_sum(ss, sred);
            float inv = rsqrtf(ss * (1.f / D) + 1e-5f);
            const float* l2l = ln2  + l * D;
            const float* fmk = ftmk + l * D;
            const float* fmr = ftmr + l * D;
            for (int j = tid; j < D; j += NT) {
                float yyj = g_x[j] * inv * l2l[j];
                float ff  = st_l[j];
                float a_ = fmk[j]; sbuf[j]     = yyj * a_ + ff * (1.f - a_);
                float b_ = fmr[j]; sbuf[D + j] = yyj * b_ + ff * (1.f - b_);
                if (blockIdx.x == 0) ost_l[j] = yyj;   // new ff_x
            }
            __syncthreads();
            const float* fkwl = fkw + (size_t)l * HD * D;
            const float* frwl = frw + (size_t)l * D * D;
            for (int row = gw; row < HD + D; row += nwG) {
                if (row < HD) {
                    float t = warp_dotN<1>(fkwl + (size_t)row * D, sbuf);
                    if (lane == 0) { t = fmaxf(t, 0.f); g_k2[row] = t * t; }
                } else {
                    float t = warp_dotN<1>(frwl + (size_t)(row - HD) * D, sbuf + D);
                    if (lane == 0) g_r2[row - HD] = t;
                }
            }
        }
        grid_barrier(nb);

        // ---------- stage D: x = (x + sigmoid(r2) * (fvw @ k2)) * sc ----------
        {
            for (int j = tid; j < HD; j += NT) sbuf[j] = g_k2[j];
            __syncthreads();
            const float sc = ((l + 1) % 6 == 0) ? 0.5f : 1.0f;
            const float* fvwl = fvw + (size_t)l * D * HD;
            for (int row = gw; row < D; row += nwG) {
                float acc = warp_dotN<4>(fvwl + (size_t)row * HD, sbuf);
                if (lane == 0) {
                    float sr = 1.f / (1.f + __expf(-g_r2[row]));
                    g_x[row] = (g_x[row] + sr * acc) * sc;
                }
            }
        }
        grid_barrier(nb);
    }

    // ---------- head: logits = head @ rms(x, lnout) ----------
    {
        float ss = 0.f;
        for (int j = tid; j < D; j += NT) { float t = g_x[j]; ss += t * t; }
        ss = block_sum(ss, sred);
        float inv = rsqrtf(ss * (1.f / D) + 1e-5f);
        for (int j = tid; j < D; j += NT) sbuf[j] = g_x[j] * inv * lnout[j];
        __syncthreads();
        for (int row = gw; row < VOCAB; row += nwG) {
            float t = warp_dotN<1>(head + (size_t)row * D, sbuf);
            if (lane == 0) out_logits[row] = t;
        }
    }
}

extern "C" void kernel_launch(void* const* d_in, const int* in_sizes, int n_in,
                              void* d_out, int out_size) {
    (void)in_sizes; (void)n_in; (void)out_size;
    int nb = 0;
    cudaDeviceGetAttribute(&nb, cudaDevAttrMultiProcessorCount, 0);
    if (nb <= 0) nb = 148;
    if (nb > 1024) nb = 1024;

    rwkv_persistent<<<nb, NT>>>(
        (const int*)  d_in[0],   // ctx
        (const float*)d_in[1],   // state
        (const float*)d_in[2],   // emb
        (const float*)d_in[3],   // ln0_w
        (const float*)d_in[4],   // ln1_w
        (const float*)d_in[5],   // ln2_w
        (const float*)d_in[6],   // lnout_w
        (const float*)d_in[7],   // att_tmk
        (const float*)d_in[8],   // att_tmv
        (const float*)d_in[9],   // att_tmr
        (const float*)d_in[10],  // att_tfirst
        (const float*)d_in[11],  // att_tdecay
        (const float*)d_in[12],  // att_kw
        (const float*)d_in[13],  // att_vw
        (const float*)d_in[14],  // att_rw
        (const float*)d_in[15],  // att_ow
        (const float*)d_in[16],  // ffn_tmk
        (const float*)d_in[17],  // ffn_tmr
        (const float*)d_in[18],  // ffn_kw
        (const float*)d_in[19],  // ffn_vw
        (const float*)d_in[20],  // ffn_rw
        (const float*)d_in[21],  // head
        (float*)d_out, nb);
}